// round 5
// baseline (speedup 1.0000x reference)
#include <cuda_runtime.h>

#define BATCH   64
#define HW      5456
#define NCH     85
#define NCLS    80
#define NTOP    100
#define CAP     24576
#define PER_IMG (HW * NCH)        /* 463760 floats per image */
#define TOTAL_ROWS (BATCH * HW)   /* 349184 */
#define T_CAND  2.0f
#define T_CHECK 2.73f
#define FLATMAX 524287            /* 2^19 - 1; flat = c*HW+hw < 436480 */

// Scratch (static device globals: allowed; runtime allocation is not)
__device__ unsigned long long g_cand[BATCH][CAP];  // ~12.6 MB
__device__ int g_cnt[BATCH];
__device__ int g_safe[BATCH];

// ---------------------------------------------------------------------------
// Bit-exact XLA-style sigmoid: 1 / (1 + expf(-x)), div.rn, no contraction.
__device__ __forceinline__ float xla_sigmoid(float x) {
    return __fdiv_rn(1.0f, __fadd_rn(1.0f, expf(-x)));
}

__device__ __forceinline__ unsigned long long make_key(float score, int flat) {
    // score in (0,1): positive float bits are order-preserving as uint.
    // Larger key = better: score desc, then smaller flat index (class-major) wins.
    return ((unsigned long long)__float_as_uint(score) << 19)
         | (unsigned)(FLATMAX - flat);
}

// ---------------------------------------------------------------------------
__global__ void k_reset() {
    if (threadIdx.x < BATCH) { g_cnt[threadIdx.x] = 0; g_safe[threadIdx.x] = 0; }
}

// ---------------------------------------------------------------------------
// Kernel 1: stream all cls logits; append candidates with raw logit >= T_CAND,
// and count logits >= T_CHECK (safety certificate for the pruning bound).
// One warp processes contiguous rows of 85 floats (fully coalesced LDG.32).
__global__ void k_filter(const float* __restrict__ pred) {
    const int lane = threadIdx.x & 31;
    const int warpsTotal = (gridDim.x * blockDim.x) >> 5;
    const int gw = (blockIdx.x * blockDim.x + threadIdx.x) >> 5;
    const int chunk = (TOTAL_ROWS + warpsTotal - 1) / warpsTotal;
    int r0 = gw * chunk;
    int r1 = min(r0 + chunk, TOTAL_ROWS);
    if (r0 >= r1) return;

    int b  = r0 / HW;
    int hw = r0 - b * HW;
    int safeAcc = 0;

    for (int r = r0; r < r1; ++r) {
        const float* row = pred + (size_t)r * NCH;
        float v0 = row[lane];           // channels 0..31
        float v1 = row[lane + 32];      // channels 32..63
        float v2 = (lane < 21) ? row[lane + 64] : -1e30f;  // channels 64..84
        bool p0 = v0 >= T_CAND;
        bool p1 = v1 >= T_CAND;
        bool p2 = (lane < 16) && (v2 >= T_CAND);  // only channels 64..79 are cls
        unsigned m0 = __ballot_sync(0xFFFFFFFFu, p0);
        unsigned m1 = __ballot_sync(0xFFFFFFFFu, p1);
        unsigned m2 = __ballot_sync(0xFFFFFFFFu, p2);
        if (m0 | m1 | m2) {
            int tot = __popc(m0) + __popc(m1) + __popc(m2);
            int base;
            if (lane == 0) base = atomicAdd(&g_cnt[b], tot);
            base = __shfl_sync(0xFFFFFFFFu, base, 0);
            unsigned lt = (1u << lane) - 1u;
            if (p0) {
                int o = base + __popc(m0 & lt);
                if (o < CAP)
                    g_cand[b][o] = ((unsigned long long)__float_as_uint(v0) << 32)
                                 | (unsigned)(lane * HW + hw);
            }
            int b1 = base + __popc(m0);
            if (p1) {
                int o = b1 + __popc(m1 & lt);
                if (o < CAP)
                    g_cand[b][o] = ((unsigned long long)__float_as_uint(v1) << 32)
                                 | (unsigned)((lane + 32) * HW + hw);
            }
            int b2 = b1 + __popc(m1);
            if (p2) {
                int o = b2 + __popc(m2 & lt);
                if (o < CAP)
                    g_cand[b][o] = ((unsigned long long)__float_as_uint(v2) << 32)
                                 | (unsigned)((lane + 64) * HW + hw);
            }
            safeAcc += (int)(p0 && v0 >= T_CHECK)
                     + (int)(p1 && v1 >= T_CHECK)
                     + (int)(p2 && v2 >= T_CHECK);
        }
        if (++hw == HW) {
            int s = safeAcc;
            s += __shfl_xor_sync(0xFFFFFFFFu, s, 16);
            s += __shfl_xor_sync(0xFFFFFFFFu, s, 8);
            s += __shfl_xor_sync(0xFFFFFFFFu, s, 4);
            s += __shfl_xor_sync(0xFFFFFFFFu, s, 2);
            s += __shfl_xor_sync(0xFFFFFFFFu, s, 1);
            if (lane == 0 && s) atomicAdd(&g_safe[b], s);
            safeAcc = 0;
            hw = 0; ++b;
        }
    }
    {
        int s = safeAcc;
        s += __shfl_xor_sync(0xFFFFFFFFu, s, 16);
        s += __shfl_xor_sync(0xFFFFFFFFu, s, 8);
        s += __shfl_xor_sync(0xFFFFFFFFu, s, 4);
        s += __shfl_xor_sync(0xFFFFFFFFu, s, 2);
        s += __shfl_xor_sync(0xFFFFFFFFu, s, 1);
        if (lane == 0 && s) atomicAdd(&g_safe[b], s);
    }
}

// ---------------------------------------------------------------------------
// Kernel 2: one block per image. Exact scores for candidates, radix-select the
// exact 100th composite key, sort top-100, decode boxes, class-aware NMS, write.
__global__ void __launch_bounds__(512) k_topk_nms(const float* __restrict__ pred,
                                                  const float* __restrict__ pixloc,
                                                  float* __restrict__ out) {
    const int b = blockIdx.x;
    const int tid = threadIdx.x;
    const int NT = 512;

    __shared__ int s_hist[256];
    __shared__ unsigned long long s_prefix;
    __shared__ int s_rank;
    __shared__ int s_n;
    __shared__ int s_cnt;
    __shared__ unsigned long long s_top[128];
    __shared__ float s_x1[NTOP], s_y1[NTOP], s_x2[NTOP], s_y2[NTOP];
    __shared__ float s_area[NTOP], s_sc[NTOP];
    __shared__ int s_cls[NTOP];
    __shared__ unsigned s_supp[NTOP][4];
    __shared__ unsigned s_keep[4];

    const float* base = pred + (size_t)b * PER_IMG;

    if (tid == 0) {
        int nn = g_cnt[b];
        bool safe = (g_safe[b] >= NTOP) && (nn <= CAP) && (nn >= NTOP);
        if (safe) {
            s_n = nn;
        } else {
            // Brute-force fallback (correct for any data; never expected here).
            unsigned long long best[NTOP];
            int nb = 0, minidx = 0;
            unsigned long long minkey = 0;
            for (int hw = 0; hw < HW; ++hw) {
                float e = __fsub_rn(2.0f, xla_sigmoid(base[hw * NCH + NCLS + 4]));
                for (int c = 0; c < NCLS; ++c) {
                    float s = xla_sigmoid(base[hw * NCH + c]);
                    if (nb == NTOP &&
                        __float_as_uint(s) < (unsigned)(minkey >> 19)) continue;
                    float sc = powf(s, e);
                    unsigned long long key = make_key(sc, c * HW + hw);
                    if (nb < NTOP) {
                        best[nb++] = key;
                        if (nb == NTOP) {
                            minkey = best[0]; minidx = 0;
                            for (int i = 1; i < NTOP; ++i)
                                if (best[i] < minkey) { minkey = best[i]; minidx = i; }
                        }
                    } else if (key > minkey) {
                        best[minidx] = key;
                        minkey = best[0]; minidx = 0;
                        for (int i = 1; i < NTOP; ++i)
                            if (best[i] < minkey) { minkey = best[i]; minidx = i; }
                    }
                }
            }
            for (int i = 0; i < NTOP; ++i) g_cand[b][i] = best[i];
            s_n = -NTOP;   // negative = keys already final
        }
        s_prefix = 0ULL;
        s_rank = NTOP;
        s_cnt = 0;
    }
    __syncthreads();

    int n = s_n;
    bool prescored = (n < 0);
    if (prescored) n = -n;

    // Phase 1: exact scoring of candidates -> composite keys (in place).
    if (!prescored) {
        for (int i = tid; i < n; i += NT) {
            unsigned long long cd = g_cand[b][i];
            unsigned flat = (unsigned)(cd & 0xFFFFFFFFu);
            float x = __uint_as_float((unsigned)(cd >> 32));
            int hw = (int)(flat % HW);
            float e = __fsub_rn(2.0f, xla_sigmoid(__ldg(base + hw * NCH + NCLS + 4)));
            float s = xla_sigmoid(x);
            float sc = powf(s, e);
            g_cand[b][i] = make_key(sc, (int)flat);
        }
    }
    __syncthreads();

    // Phase 2: MSB radix-select the exact 100th-largest key (keys are unique).
    unsigned long long prefix = 0ULL;
    for (int d = 6; d >= 0; --d) {
        if (tid < 256) s_hist[tid] = 0;
        __syncthreads();
        unsigned long long hmask = (~0ULL) << (8 * (d + 1));
        for (int i = tid; i < n; i += NT) {
            unsigned long long k = g_cand[b][i];
            if (((k ^ prefix) & hmask) == 0ULL)
                atomicAdd(&s_hist[(int)((k >> (8 * d)) & 255)], 1);
        }
        __syncthreads();
        if (tid == 0) {
            int r = s_rank;
            int v = 255;
            for (; v > 0; --v) {
                int h = s_hist[v];
                if (h >= r) break;
                r -= h;
            }
            s_rank = r;
            s_prefix = prefix | ((unsigned long long)v << (8 * d));
        }
        __syncthreads();
        prefix = s_prefix;
    }
    unsigned long long kth = prefix;

    // Phase 3: compact the exactly-100 keys >= kth.
    for (int i = tid; i < n; i += NT) {
        unsigned long long k = g_cand[b][i];
        if (k >= kth) {
            int p = atomicAdd(&s_cnt, 1);
            if (p < 128) s_top[p] = k;
        }
    }
    __syncthreads();
    if (tid < 128 && tid >= s_cnt) s_top[tid] = 0ULL;
    __syncthreads();

    // Phase 4: bitonic sort 128 keys descending.
    for (int k = 2; k <= 128; k <<= 1) {
        for (int j = k >> 1; j > 0; j >>= 1) {
            if (tid < 128) {
                int ixj = tid ^ j;
                if (ixj > tid) {
                    unsigned long long a = s_top[tid], c = s_top[ixj];
                    bool up = (tid & k) == 0;  // descending
                    if (up ? (a < c) : (a > c)) { s_top[tid] = c; s_top[ixj] = a; }
                }
            }
            __syncthreads();
        }
    }

    // Phase 5: decode boxes for the top-100 (bit-exact: no FMA contraction).
    if (tid < NTOP) {
        unsigned long long key = s_top[tid];
        int flat = FLATMAX - (int)(key & 0x7FFFF);
        int c = flat / HW;
        int hw = flat - c * HW;
        float sc = __uint_as_float((unsigned)(key >> 19));
        const float* rp = base + hw * NCH;
        float e0 = expf(rp[80]);
        float e1 = expf(rp[81]);
        float e2 = expf(rp[82]);
        float e3 = expf(rp[83]);
        float x1 = __fadd_rn(__fmul_rn(e0, -1.0f), pixloc[4 * hw + 0]);
        float y1 = __fadd_rn(__fmul_rn(e1, -1.0f), pixloc[4 * hw + 1]);
        float x2 = __fadd_rn(__fmul_rn(e2,  1.0f), pixloc[4 * hw + 2]);
        float y2 = __fadd_rn(__fmul_rn(e3,  1.0f), pixloc[4 * hw + 3]);
        s_x1[tid] = x1; s_y1[tid] = y1; s_x2[tid] = x2; s_y2[tid] = y2;
        s_area[tid] = __fmul_rn(__fsub_rn(x2, x1), __fsub_rn(y2, y1));
        s_sc[tid] = sc;
        s_cls[tid] = c;
    }
    if (tid < NTOP * 4) ((unsigned*)s_supp)[tid] = 0u;
    __syncthreads();

    // Phase 6: suppress matrix (iou > 0.5, same class, j later than i).
    for (int p = tid; p < NTOP * NTOP; p += NT) {
        int i = p / NTOP, j = p - i * NTOP;
        if (j > i && s_cls[i] == s_cls[j]) {
            float xx1 = fmaxf(s_x1[i], s_x1[j]);
            float yy1 = fmaxf(s_y1[i], s_y1[j]);
            float xx2 = fminf(s_x2[i], s_x2[j]);
            float yy2 = fminf(s_y2[i], s_y2[j]);
            float w = fmaxf(1e-28f, __fsub_rn(xx2, xx1));
            float h = fmaxf(1e-28f, __fsub_rn(yy2, yy1));
            float inter = __fmul_rn(w, h);
            float iou = __fdiv_rn(inter,
                __fsub_rn(__fadd_rn(s_area[i], s_area[j]), inter));
            if (iou > 0.5f) atomicOr(&s_supp[i][j >> 5], 1u << (j & 31));
        }
    }
    __syncthreads();

    // Phase 7: serial greedy keep (inherently sequential; tiny).
    if (tid == 0) {
        unsigned km[4] = {0u, 0u, 0u, 0u};
        for (int k = 0; k < NTOP; ++k)
            if (s_sc[k] >= 0.05f) km[k >> 5] |= 1u << (k & 31);
        for (int i = 0; i < NTOP; ++i) {
            if ((km[i >> 5] >> (i & 31)) & 1u) {
                km[0] &= ~s_supp[i][0];
                km[1] &= ~s_supp[i][1];
                km[2] &= ~s_supp[i][2];
                km[3] &= ~s_supp[i][3];
            }
        }
        s_keep[0] = km[0]; s_keep[1] = km[1]; s_keep[2] = km[2]; s_keep[3] = km[3];
    }
    __syncthreads();

    // Phase 8: outputs, concatenated flattened tuple:
    // boxes [B,100,4] | scores [B,100] | cls [B,100] | keep [B,100], all f32.
    if (tid < NTOP) {
        const float inv = 1.0f / 512.0f;   // power of two: exact
        float b0 = fminf(fmaxf(s_x1[tid], 0.0f), 511.0f) * inv;
        float b1 = fminf(fmaxf(s_y1[tid], 0.0f), 511.0f) * inv;
        float b2 = fminf(fmaxf(s_x2[tid], 0.0f), 511.0f) * inv;
        float b3 = fminf(fmaxf(s_y2[tid], 0.0f), 511.0f) * inv;
        int boff = (b * NTOP + tid) * 4;
        out[boff + 0] = b0;
        out[boff + 1] = b1;
        out[boff + 2] = b2;
        out[boff + 3] = b3;
        out[BATCH * NTOP * 4 + b * NTOP + tid] = s_sc[tid];
        out[BATCH * NTOP * 5 + b * NTOP + tid] = (float)s_cls[tid];
        out[BATCH * NTOP * 6 + b * NTOP + tid] =
            ((s_keep[tid >> 5] >> (tid & 31)) & 1u) ? 1.0f : 0.0f;
    }
}

// ---------------------------------------------------------------------------
extern "C" void kernel_launch(void* const* d_in, const int* in_sizes, int n_in,
                              void* d_out, int out_size) {
    const float* pred   = (const float*)d_in[0];   // (64, 5456, 85) f32
    const float* pixloc = (const float*)d_in[1];   // (5456, 4) f32
    float* out = (float*)d_out;

    k_reset<<<1, 64>>>();
    k_filter<<<1024, 256>>>(pred);
    k_topk_nms<<<BATCH, 512>>>(pred, pixloc, out);
}

// round 6
// speedup vs baseline: 2.2339x; 2.2339x over previous
#include <cuda_runtime.h>

#define BATCH   64
#define HW      5456
#define NCH     85
#define NCLS    80
#define NTOP    100
#define CAP     24576
#define PER_IMG (HW * NCH)        /* 463760 floats per image */
#define T_CAND  2.0f
#define T_CHECK 2.73f
#define FLATMAX 524287            /* 2^19 - 1; flat = c*HW+hw < 436480 */

#define SEGS    16                /* blocks per image in k_filter */
#define SEG_ROWS (HW / SEGS)      /* 341 */
#define SBUF    2048              /* smem staging capacity per block */
#define CPAD    32                /* counter padding: 32 ints = 128 B */

// Scratch (static device globals: allowed; runtime allocation is not)
__device__ unsigned long long g_cand[BATCH][CAP];  // ~12.6 MB
__device__ int g_cnt[BATCH * CPAD];
__device__ int g_safe[BATCH * CPAD];

// ---------------------------------------------------------------------------
// Bit-exact XLA-style sigmoid: 1 / (1 + expf(-x)), div.rn, no contraction.
__device__ __forceinline__ float xla_sigmoid(float x) {
    return __fdiv_rn(1.0f, __fadd_rn(1.0f, expf(-x)));
}

__device__ __forceinline__ unsigned long long make_key(float score, int flat) {
    // score in (0,1): positive float bits are order-preserving as uint.
    // Larger key = better: score desc, then smaller flat index (class-major) wins.
    return ((unsigned long long)__float_as_uint(score) << 19)
         | (unsigned)(FLATMAX - flat);
}

// ---------------------------------------------------------------------------
__global__ void k_reset() {
    int i = blockIdx.x * blockDim.x + threadIdx.x;
    if (i < BATCH * CPAD) { g_cnt[i] = 0; g_safe[i] = 0; }
}

// ---------------------------------------------------------------------------
// Kernel 1: stream all cls logits; stage candidates (raw logit >= T_CAND) in
// shared memory, then ONE padded global atomic per block. Also count logits
// >= T_CHECK (safety certificate for the pruning bound).
// Grid: BATCH*SEGS blocks of 256 threads; warp-per-row, coalesced LDG.32.
__global__ void __launch_bounds__(256) k_filter(const float* __restrict__ pred) {
    __shared__ unsigned long long s_buf[SBUF];
    __shared__ int s_cnt, s_safe, s_base;

    const int b   = blockIdx.x / SEGS;
    const int seg = blockIdx.x % SEGS;
    const int lane = threadIdx.x & 31;
    const int warp = threadIdx.x >> 5;

    if (threadIdx.x == 0) { s_cnt = 0; s_safe = 0; }
    __syncthreads();

    // Warp w handles contiguous local rows [w*43, min((w+1)*43, 341))
    const int lr0 = warp * 43;
    const int lr1 = min(lr0 + 43, SEG_ROWS);
    const float* imgBase = pred + (size_t)b * PER_IMG;

    int safeAcc = 0;
    for (int lr = lr0; lr < lr1; ++lr) {
        const int hw = seg * SEG_ROWS + lr;
        const float* row = imgBase + (size_t)hw * NCH;
        float v0 = row[lane];           // channels 0..31
        float v1 = row[lane + 32];      // channels 32..63
        float v2 = (lane < 21) ? row[lane + 64] : -1e30f;  // channels 64..84
        bool p0 = v0 >= T_CAND;
        bool p1 = v1 >= T_CAND;
        bool p2 = (lane < 16) && (v2 >= T_CAND);  // only channels 64..79 are cls
        unsigned m0 = __ballot_sync(0xFFFFFFFFu, p0);
        unsigned m1 = __ballot_sync(0xFFFFFFFFu, p1);
        unsigned m2 = __ballot_sync(0xFFFFFFFFu, p2);
        if (m0 | m1 | m2) {
            int tot = __popc(m0) + __popc(m1) + __popc(m2);
            int base;
            if (lane == 0) base = atomicAdd(&s_cnt, tot);   // cheap smem atomic
            base = __shfl_sync(0xFFFFFFFFu, base, 0);
            unsigned lt = (1u << lane) - 1u;
            if (p0) {
                int o = base + __popc(m0 & lt);
                if (o < SBUF)
                    s_buf[o] = ((unsigned long long)__float_as_uint(v0) << 32)
                             | (unsigned)(lane * HW + hw);
            }
            int b1 = base + __popc(m0);
            if (p1) {
                int o = b1 + __popc(m1 & lt);
                if (o < SBUF)
                    s_buf[o] = ((unsigned long long)__float_as_uint(v1) << 32)
                             | (unsigned)((lane + 32) * HW + hw);
            }
            int b2 = b1 + __popc(m1);
            if (p2) {
                int o = b2 + __popc(m2 & lt);
                if (o < SBUF)
                    s_buf[o] = ((unsigned long long)__float_as_uint(v2) << 32)
                             | (unsigned)((lane + 64) * HW + hw);
            }
            safeAcc += (int)(p0 && v0 >= T_CHECK)
                     + (int)(p1 && v1 >= T_CHECK)
                     + (int)(p2 && v2 >= T_CHECK);
        }
    }
    // warp-reduce safe count, one smem atomic per warp
    {
        int s = safeAcc;
        s += __shfl_xor_sync(0xFFFFFFFFu, s, 16);
        s += __shfl_xor_sync(0xFFFFFFFFu, s, 8);
        s += __shfl_xor_sync(0xFFFFFFFFu, s, 4);
        s += __shfl_xor_sync(0xFFFFFFFFu, s, 2);
        s += __shfl_xor_sync(0xFFFFFFFFu, s, 1);
        if (lane == 0 && s) atomicAdd(&s_safe, s);
    }
    __syncthreads();

    // ONE global atomic per block (padded counters -> distinct L2 lines).
    if (threadIdx.x == 0) {
        int total = s_cnt;
        // If smem staging overflowed (deterministically never with this data),
        // poison the count past CAP so k_topk_nms takes the exact fallback.
        int claim = (total > SBUF) ? (CAP + 1000) : total;
        s_base = atomicAdd(&g_cnt[b * CPAD], claim);
        if (s_safe) atomicAdd(&g_safe[b * CPAD], s_safe);
    }
    __syncthreads();

    // Coalesced bulk copy of staged candidates to the image's global buffer.
    int total = min(s_cnt, SBUF);
    int gbase = s_base;
    for (int i = threadIdx.x; i < total; i += 256) {
        int o = gbase + i;
        if (o < CAP) g_cand[b][o] = s_buf[i];
    }
}

// ---------------------------------------------------------------------------
// Kernel 2: one block per image. Exact scores for candidates, radix-select the
// exact 100th composite key, sort top-100, decode boxes, class-aware NMS, write.
__global__ void __launch_bounds__(512) k_topk_nms(const float* __restrict__ pred,
                                                  const float* __restrict__ pixloc,
                                                  float* __restrict__ out) {
    const int b = blockIdx.x;
    const int tid = threadIdx.x;
    const int NT = 512;

    __shared__ int s_hist[256];
    __shared__ unsigned long long s_prefix;
    __shared__ int s_rank;
    __shared__ int s_n;
    __shared__ int s_cnt;
    __shared__ unsigned long long s_top[128];
    __shared__ float s_x1[NTOP], s_y1[NTOP], s_x2[NTOP], s_y2[NTOP];
    __shared__ float s_area[NTOP], s_sc[NTOP];
    __shared__ int s_cls[NTOP];
    __shared__ unsigned s_supp[NTOP][4];
    __shared__ unsigned s_keep[4];

    const float* base = pred + (size_t)b * PER_IMG;

    if (tid == 0) {
        int nn = g_cnt[b * CPAD];
        bool safe = (g_safe[b * CPAD] >= NTOP) && (nn <= CAP) && (nn >= NTOP);
        if (safe) {
            s_n = nn;
        } else {
            // Brute-force fallback (correct for any data; never expected here).
            unsigned long long best[NTOP];
            int nb = 0, minidx = 0;
            unsigned long long minkey = 0;
            for (int hw = 0; hw < HW; ++hw) {
                float e = __fsub_rn(2.0f, xla_sigmoid(base[hw * NCH + NCLS + 4]));
                for (int c = 0; c < NCLS; ++c) {
                    float s = xla_sigmoid(base[hw * NCH + c]);
                    if (nb == NTOP &&
                        __float_as_uint(s) < (unsigned)(minkey >> 19)) continue;
                    float sc = powf(s, e);
                    unsigned long long key = make_key(sc, c * HW + hw);
                    if (nb < NTOP) {
                        best[nb++] = key;
                        if (nb == NTOP) {
                            minkey = best[0]; minidx = 0;
                            for (int i = 1; i < NTOP; ++i)
                                if (best[i] < minkey) { minkey = best[i]; minidx = i; }
                        }
                    } else if (key > minkey) {
                        best[minidx] = key;
                        minkey = best[0]; minidx = 0;
                        for (int i = 1; i < NTOP; ++i)
                            if (best[i] < minkey) { minkey = best[i]; minidx = i; }
                    }
                }
            }
            for (int i = 0; i < NTOP; ++i) g_cand[b][i] = best[i];
            s_n = -NTOP;   // negative = keys already final
        }
        s_prefix = 0ULL;
        s_rank = NTOP;
        s_cnt = 0;
    }
    __syncthreads();

    int n = s_n;
    bool prescored = (n < 0);
    if (prescored) n = -n;

    // Phase 1: exact scoring of candidates -> composite keys (in place).
    if (!prescored) {
        for (int i = tid; i < n; i += NT) {
            unsigned long long cd = g_cand[b][i];
            unsigned flat = (unsigned)(cd & 0xFFFFFFFFu);
            float x = __uint_as_float((unsigned)(cd >> 32));
            int hw = (int)(flat % HW);
            float e = __fsub_rn(2.0f, xla_sigmoid(__ldg(base + hw * NCH + NCLS + 4)));
            float s = xla_sigmoid(x);
            float sc = powf(s, e);
            g_cand[b][i] = make_key(sc, (int)flat);
        }
    }
    __syncthreads();

    // Phase 2: MSB radix-select the exact 100th-largest key (keys are unique).
    unsigned long long prefix = 0ULL;
    for (int d = 6; d >= 0; --d) {
        if (tid < 256) s_hist[tid] = 0;
        __syncthreads();
        unsigned long long hmask = (~0ULL) << (8 * (d + 1));
        for (int i = tid; i < n; i += NT) {
            unsigned long long k = g_cand[b][i];
            if (((k ^ prefix) & hmask) == 0ULL)
                atomicAdd(&s_hist[(int)((k >> (8 * d)) & 255)], 1);
        }
        __syncthreads();
        if (tid == 0) {
            int r = s_rank;
            int v = 255;
            for (; v > 0; --v) {
                int h = s_hist[v];
                if (h >= r) break;
                r -= h;
            }
            s_rank = r;
            s_prefix = prefix | ((unsigned long long)v << (8 * d));
        }
        __syncthreads();
        prefix = s_prefix;
    }
    unsigned long long kth = prefix;

    // Phase 3: compact the exactly-100 keys >= kth.
    for (int i = tid; i < n; i += NT) {
        unsigned long long k = g_cand[b][i];
        if (k >= kth) {
            int p = atomicAdd(&s_cnt, 1);
            if (p < 128) s_top[p] = k;
        }
    }
    __syncthreads();
    if (tid < 128 && tid >= s_cnt) s_top[tid] = 0ULL;
    __syncthreads();

    // Phase 4: bitonic sort 128 keys descending.
    for (int k = 2; k <= 128; k <<= 1) {
        for (int j = k >> 1; j > 0; j >>= 1) {
            if (tid < 128) {
                int ixj = tid ^ j;
                if (ixj > tid) {
                    unsigned long long a = s_top[tid], c = s_top[ixj];
                    bool up = (tid & k) == 0;  // descending
                    if (up ? (a < c) : (a > c)) { s_top[tid] = c; s_top[ixj] = a; }
                }
            }
            __syncthreads();
        }
    }

    // Phase 5: decode boxes for the top-100 (bit-exact: no FMA contraction).
    if (tid < NTOP) {
        unsigned long long key = s_top[tid];
        int flat = FLATMAX - (int)(key & 0x7FFFF);
        int c = flat / HW;
        int hw = flat - c * HW;
        float sc = __uint_as_float((unsigned)(key >> 19));
        const float* rp = base + hw * NCH;
        float e0 = expf(rp[80]);
        float e1 = expf(rp[81]);
        float e2 = expf(rp[82]);
        float e3 = expf(rp[83]);
        float x1 = __fadd_rn(__fmul_rn(e0, -1.0f), pixloc[4 * hw + 0]);
        float y1 = __fadd_rn(__fmul_rn(e1, -1.0f), pixloc[4 * hw + 1]);
        float x2 = __fadd_rn(__fmul_rn(e2,  1.0f), pixloc[4 * hw + 2]);
        float y2 = __fadd_rn(__fmul_rn(e3,  1.0f), pixloc[4 * hw + 3]);
        s_x1[tid] = x1; s_y1[tid] = y1; s_x2[tid] = x2; s_y2[tid] = y2;
        s_area[tid] = __fmul_rn(__fsub_rn(x2, x1), __fsub_rn(y2, y1));
        s_sc[tid] = sc;
        s_cls[tid] = c;
    }
    if (tid < NTOP * 4) ((unsigned*)s_supp)[tid] = 0u;
    __syncthreads();

    // Phase 6: suppress matrix (iou > 0.5, same class, j later than i).
    for (int p = tid; p < NTOP * NTOP; p += NT) {
        int i = p / NTOP, j = p - i * NTOP;
        if (j > i && s_cls[i] == s_cls[j]) {
            float xx1 = fmaxf(s_x1[i], s_x1[j]);
            float yy1 = fmaxf(s_y1[i], s_y1[j]);
            float xx2 = fminf(s_x2[i], s_x2[j]);
            float yy2 = fminf(s_y2[i], s_y2[j]);
            float w = fmaxf(1e-28f, __fsub_rn(xx2, xx1));
            float h = fmaxf(1e-28f, __fsub_rn(yy2, yy1));
            float inter = __fmul_rn(w, h);
            float iou = __fdiv_rn(inter,
                __fsub_rn(__fadd_rn(s_area[i], s_area[j]), inter));
            if (iou > 0.5f) atomicOr(&s_supp[i][j >> 5], 1u << (j & 31));
        }
    }
    __syncthreads();

    // Phase 7: serial greedy keep (inherently sequential; tiny).
    if (tid == 0) {
        unsigned km[4] = {0u, 0u, 0u, 0u};
        for (int k = 0; k < NTOP; ++k)
            if (s_sc[k] >= 0.05f) km[k >> 5] |= 1u << (k & 31);
        for (int i = 0; i < NTOP; ++i) {
            if ((km[i >> 5] >> (i & 31)) & 1u) {
                km[0] &= ~s_supp[i][0];
                km[1] &= ~s_supp[i][1];
                km[2] &= ~s_supp[i][2];
                km[3] &= ~s_supp[i][3];
            }
        }
        s_keep[0] = km[0]; s_keep[1] = km[1]; s_keep[2] = km[2]; s_keep[3] = km[3];
    }
    __syncthreads();

    // Phase 8: outputs, concatenated flattened tuple:
    // boxes [B,100,4] | scores [B,100] | cls [B,100] | keep [B,100], all f32.
    if (tid < NTOP) {
        const float inv = 1.0f / 512.0f;   // power of two: exact
        float b0 = fminf(fmaxf(s_x1[tid], 0.0f), 511.0f) * inv;
        float b1 = fminf(fmaxf(s_y1[tid], 0.0f), 511.0f) * inv;
        float b2 = fminf(fmaxf(s_x2[tid], 0.0f), 511.0f) * inv;
        float b3 = fminf(fmaxf(s_y2[tid], 0.0f), 511.0f) * inv;
        int boff = (b * NTOP + tid) * 4;
        out[boff + 0] = b0;
        out[boff + 1] = b1;
        out[boff + 2] = b2;
        out[boff + 3] = b3;
        out[BATCH * NTOP * 4 + b * NTOP + tid] = s_sc[tid];
        out[BATCH * NTOP * 5 + b * NTOP + tid] = (float)s_cls[tid];
        out[BATCH * NTOP * 6 + b * NTOP + tid] =
            ((s_keep[tid >> 5] >> (tid & 31)) & 1u) ? 1.0f : 0.0f;
    }
}

// ---------------------------------------------------------------------------
extern "C" void kernel_launch(void* const* d_in, const int* in_sizes, int n_in,
                              void* d_out, int out_size) {
    const float* pred   = (const float*)d_in[0];   // (64, 5456, 85) f32
    const float* pixloc = (const float*)d_in[1];   // (5456, 4) f32
    float* out = (float*)d_out;

    k_reset<<<(BATCH * CPAD + 255) / 256, 256>>>();
    k_filter<<<BATCH * SEGS, 256>>>(pred);
    k_topk_nms<<<BATCH, 512>>>(pred, pixloc, out);
}